// round 15
// baseline (speedup 1.0000x reference)
#include <cuda_runtime.h>
#include <cuda_bf16.h>
#include <cuda_fp16.h>
#include <cstdint>

#define NMAX   50000
#define EMAX   800000
#define DD     128
#define NRELMX 237

// SMEM (bytes): A fp16 [64][136], B fp16 [256][136]
#define SA      136
#define A_OFF   0
#define B_OFF   17408
#define SM_BYTES 87040
// staging reuse: Ysh [64][136] fp16 at 0; H at 17408 (fp32 [64][132] or fp16 [64][136])
#define YS_OFF  0
#define HS_OFF  17408

// ---------------- static device scratch ------------------------------------
__device__ __half g_Yh[2][(size_t)NMAX * DD]; // per-layer Y fp16 (edge gather)
__device__ __half g_Hh[(size_t)NMAX * DD];    // layer-1 hidden base fp16
__device__ float  g_R[2][NRELMX * DD];        // rel @ W_I^T per layer (fp32)
__device__ __half g_Rh[2][NRELMX * DD];       // fp16 copies (edge gather)
__device__ int    g_cnt[NMAX];
__device__ int    g_rowstart[NMAX + 1];
__device__ int    g_edata[EMAX];              // packed (src<<8)|etype
// Pre-packed B image [256][136] fp16 (interleaved Y/Z cols)
__device__ uint4 g_Bhi[(256 * SA * 2) / 16];

// ---------------- PTX helpers ------------------------------------------------
__device__ __forceinline__ uint32_t smem_to_u32(const void* p) {
    uint32_t a;
    asm("{ .reg .u64 t; cvta.to.shared.u64 t, %1; cvt.u32.u64 %0, t; }" : "=r"(a) : "l"(p));
    return a;
}
__device__ __forceinline__ void ldmx4(uint32_t* r, uint32_t addr) {
    asm volatile("ldmatrix.sync.aligned.m8n8.x4.shared.b16 {%0,%1,%2,%3}, [%4];"
                 : "=r"(r[0]), "=r"(r[1]), "=r"(r[2]), "=r"(r[3]) : "r"(addr));
}
__device__ __forceinline__ void mma16816h(float* d, const uint32_t* a, const uint32_t* b) {
    asm volatile(
        "mma.sync.aligned.m16n8k16.row.col.f32.f16.f16.f32 "
        "{%0,%1,%2,%3}, {%4,%5,%6,%7}, {%8,%9}, {%0,%1,%2,%3};"
        : "+f"(d[0]), "+f"(d[1]), "+f"(d[2]), "+f"(d[3])
        : "r"(a[0]), "r"(a[1]), "r"(a[2]), "r"(a[3]), "r"(b[0]), "r"(b[1]));
}
__device__ __forceinline__ uint32_t pack_h2(__half a, __half b) {
    __half2 t = __halves2half2(a, b);
    return *reinterpret_cast<uint32_t*>(&t);
}
__device__ __forceinline__ void acc_edge(float4& acc, uint2 y, uint2 r) {
    float2 ya = __half22float2(*(__half2*)&y.x), yb = __half22float2(*(__half2*)&y.y);
    float2 ra = __half22float2(*(__half2*)&r.x), rb = __half22float2(*(__half2*)&r.y);
    acc.x += ya.x - ra.x;
    acc.y += ya.y - ra.y;
    acc.z += yb.x - rb.x;
    acc.w += yb.y - rb.y;
}

// ---------------- B pack: [256][136] fp16, cols interleaved Y/Z -------------
__global__ void packb_kernel(const float* __restrict__ W_I,
                             const float* __restrict__ W_O) {
    int idx = blockIdx.x * blockDim.x + threadIdx.x;  // 0..32767
    if (idx >= 256 * DD) return;
    int r = idx >> 7;
    int k = idx & 127;
    int c = r >> 1;
    float v = (r & 1) ? W_O[c * DD + k] : W_I[c * DD + k];
    uint32_t off = (uint32_t)(r * SA + k) * 2u;
    *(__half*)((char*)g_Bhi + off) = __float2half(v);
}

// ---------------- R[layer][r][n] = sum_k rel[r][k] * W_I[n][k] --------------
__global__ void relgemm_kernel(const float* __restrict__ rel,
                               const float* __restrict__ W_I, int layer) {
    __shared__ float rr[DD];
    int r = blockIdx.x;
    int n = threadIdx.x;
    rr[n] = rel[r * DD + n];
    __syncthreads();
    const float4* w4 = (const float4*)(W_I + n * DD);
    float s = 0.f;
#pragma unroll
    for (int kk = 0; kk < DD / 4; kk++) {
        float4 wv = w4[kk];
        s += rr[4 * kk + 0] * wv.x + rr[4 * kk + 1] * wv.y +
             rr[4 * kk + 2] * wv.z + rr[4 * kk + 3] * wv.w;
    }
    g_R[layer][r * DD + n] = s;
    g_Rh[layer][r * DD + n] = __float2half(s);
}

// ---------------- edge CSR build --------------------------------------------
__global__ void zero_kernel(int M) {
    int i = blockIdx.x * blockDim.x + threadIdx.x;
    if (i < M) g_cnt[i] = 0;
}
__global__ void hist_kernel(const int* __restrict__ dst, int E) {
    int e = blockIdx.x * blockDim.x + threadIdx.x;
    if (e < E) atomicAdd(&g_cnt[dst[e]], 1);
}
__global__ __launch_bounds__(1024) void scan_kernel(int M) {
    __shared__ int ssum[1024];
    int t = threadIdx.x;
    const int CH = (M + 1023) / 1024;
    int beg = t * CH;
    int s = 0;
    for (int i = 0; i < CH; i++) {
        int idx = beg + i;
        if (idx < M) s += g_cnt[idx];
    }
    ssum[t] = s;
    __syncthreads();
    for (int off = 1; off < 1024; off <<= 1) {
        int v = (t >= off) ? ssum[t - off] : 0;
        __syncthreads();
        ssum[t] += v;
        __syncthreads();
    }
    int pre = (t == 0) ? 0 : ssum[t - 1];
    for (int i = 0; i < CH; i++) {
        int idx = beg + i;
        if (idx < M) {
            g_rowstart[idx] = pre;
            pre += g_cnt[idx];
        }
    }
    if (t == 1023) g_rowstart[M] = pre;
}
// fill post-increments g_rowstart[d]; afterwards g_rowstart[d] == row-end(d)
__global__ void fill_kernel(const int* __restrict__ src,
                            const int* __restrict__ dst,
                            const int* __restrict__ et, int E) {
    int e = blockIdx.x * blockDim.x + threadIdx.x;
    if (e >= E) return;
    int d = dst[e];
    int pos = atomicAdd(&g_rowstart[d], 1);
    g_edata[pos] = (src[e] << 8) | et[e];
}

// ---------------- HMMA GEMM: BM=64, BN=256 n' (full 128 cols), 256 thr ------
// layer1: A = fp16(x);  layer2 (FUSED): A = relu(Hh + sum_edges(Yh0 - Rh0))
template <bool FUSED, bool TO_OUT>
__global__ __launch_bounds__(256, 2)
void gemm_mma_kernel(const float* __restrict__ Ain,
                     const float* __restrict__ bias,
                     float* __restrict__ extout, int M, int layer) {
    extern __shared__ char smem[];
    uint32_t sb = smem_to_u32(smem);
    int tid = threadIdx.x;
    int wid = tid >> 5;
    int lane = tid & 31;
    int bm = blockIdx.x * 64;

    // ---- B copy: full packed image, 4352 uint4 ----
    {
        uint4* bh = (uint4*)(smem + B_OFF);
#pragma unroll
        for (int i = 0; i < 17; i++) {
            int idx = tid + i * 256;
            if (idx < 4352) bh[idx] = g_Bhi[idx];
        }
    }

    // ---- A phase ----
    if (FUSED) {
        // per-warp rows: gather layer-1 edges + base + relu, write fp16 A
        const uint2* Yh2 = (const uint2*)g_Yh[0];
        const uint2* Rh2 = (const uint2*)g_Rh[0];
        const uint2* Hh2 = (const uint2*)g_Hh;
        for (int rr = wid; rr < 64; rr += 8) {
            int gm = bm + rr;
            uint2 store = make_uint2(0u, 0u);
            if (gm < M) {
                float4 acc = make_float4(0.f, 0.f, 0.f, 0.f);
                int beg = gm ? __ldg(&g_rowstart[gm - 1]) : 0;
                int end = __ldg(&g_rowstart[gm]);
                int i = beg;
                for (; i + 1 < end; i += 2) {
                    int e0 = __ldg(&g_edata[i]);
                    int e1 = __ldg(&g_edata[i + 1]);
                    uint2 y0 = __ldg(&Yh2[(size_t)(e0 >> 8) * 32 + lane]);
                    uint2 r0 = __ldg(&Rh2[(size_t)(e0 & 255) * 32 + lane]);
                    uint2 y1 = __ldg(&Yh2[(size_t)(e1 >> 8) * 32 + lane]);
                    uint2 r1 = __ldg(&Rh2[(size_t)(e1 & 255) * 32 + lane]);
                    acc_edge(acc, y0, r0);
                    acc_edge(acc, y1, r1);
                }
                if (i < end) {
                    int e0 = __ldg(&g_edata[i]);
                    uint2 y0 = __ldg(&Yh2[(size_t)(e0 >> 8) * 32 + lane]);
                    uint2 r0 = __ldg(&Rh2[(size_t)(e0 & 255) * 32 + lane]);
                    acc_edge(acc, y0, r0);
                }
                uint2 hb = __ldg(&Hh2[(size_t)gm * 32 + lane]);
                float2 ha = __half22float2(*(__half2*)&hb.x);
                float2 hc = __half22float2(*(__half2*)&hb.y);
                float v0 = fmaxf(ha.x + acc.x, 0.f);
                float v1 = fmaxf(ha.y + acc.y, 0.f);
                float v2 = fmaxf(hc.x + acc.z, 0.f);
                float v3 = fmaxf(hc.y + acc.w, 0.f);
                store = make_uint2(pack_h2(__float2half(v0), __float2half(v1)),
                                   pack_h2(__float2half(v2), __float2half(v3)));
            }
            *(uint2*)(smem + A_OFF + (uint32_t)(rr * SA + lane * 4) * 2u) = store;
        }
    } else {
        // fp32 X load (coalesced) + fp16 convert: 2048 float4 slots
#pragma unroll
        for (int i = 0; i < 8; i++) {
            int slot = tid + i * 256;
            int row = slot >> 5;
            int c4 = (slot & 31) * 4;
            int gm = bm + row;
            float4 v = make_float4(0.f, 0.f, 0.f, 0.f);
            if (gm < M) v = *(const float4*)(Ain + (size_t)gm * DD + c4);
            *(uint2*)(smem + A_OFF + (uint32_t)(row * SA + c4) * 2u) =
                make_uint2(pack_h2(__float2half(v.x), __float2half(v.y)),
                           pack_h2(__float2half(v.z), __float2half(v.w)));
        }
    }
    __syncthreads();

    int wm = wid & 1;        // rows wm*32..+32
    int wn = wid >> 1;       // n' cols wn*64..+64 (0..3)
    int grp = lane >> 3;
    int r8 = lane & 7;

    float acc[2][8][4];
#pragma unroll
    for (int mt = 0; mt < 2; mt++)
#pragma unroll
        for (int nt = 0; nt < 8; nt++)
#pragma unroll
            for (int q = 0; q < 4; q++) acc[mt][nt][q] = 0.f;

    uint32_t a_off = sb + A_OFF + (uint32_t)((wm * 32 + (grp & 1) * 8 + r8) * SA + (grp >> 1) * 8) * 2u;
    uint32_t b_off = sb + B_OFF + (uint32_t)((wn * 64 + (grp >> 1) * 8 + r8) * SA + (grp & 1) * 8) * 2u;

#pragma unroll
    for (int ks = 0; ks < 8; ks++) {
        uint32_t kb = (uint32_t)(ks * 16 * 2);
        uint32_t afh[2][4];
#pragma unroll
        for (int mt = 0; mt < 2; mt++)
            ldmx4(afh[mt], a_off + (uint32_t)(mt * 16 * SA * 2) + kb);
        uint32_t bfh[8][2];
#pragma unroll
        for (int np = 0; np < 4; np++) {
            uint32_t addr = b_off + (uint32_t)(np * 16 * SA * 2) + kb;
            uint32_t t[4];
            ldmx4(t, addr);
            bfh[np * 2][0] = t[0]; bfh[np * 2][1] = t[1];
            bfh[np * 2 + 1][0] = t[2]; bfh[np * 2 + 1][1] = t[3];
        }
#pragma unroll
        for (int mt = 0; mt < 2; mt++)
#pragma unroll
            for (int nt = 0; nt < 8; nt++)
                mma16816h(acc[mt][nt], afh[mt], bfh[nt]);
    }
    __syncthreads();   // done with A/B smem; reuse for staging

    // ---- stage: Ysh[64][136] fp16; H fp32 [64][132] or fp16 [64][136] ----
    __half* Ysh = (__half*)(smem + YS_OFF);
    __half* Hsh = (__half*)(smem + HS_OFF);
    float*  Hs  = (float*)(smem + HS_OFF);
    const float* Rb = g_R[layer];
#pragma unroll
    for (int nt = 0; nt < 8; nt++) {
        int cl = wn * 32 + nt * 4 + (lane & 3);   // real col 0..127
        float rb = bias[cl] - Rb[cl];
#pragma unroll
        for (int mt = 0; mt < 2; mt++) {
            int r0 = wm * 32 + mt * 16 + (lane >> 2);
            float y0 = acc[mt][nt][0], z0 = acc[mt][nt][1];
            float y1 = acc[mt][nt][2], z1 = acc[mt][nt][3];
            Ysh[r0 * SA + cl] = __float2half(y0);
            Ysh[(r0 + 8) * SA + cl] = __float2half(y1);
            if (TO_OUT) {
                Hs[r0 * 132 + cl] = y0 + z0 + rb;
                Hs[(r0 + 8) * 132 + cl] = y1 + z1 + rb;
            } else {
                Hsh[r0 * SA + cl] = __float2half(y0 + z0 + rb);
                Hsh[(r0 + 8) * SA + cl] = __float2half(y1 + z1 + rb);
            }
        }
    }
    __syncthreads();

    // ---- coalesced copy-out: 64 rows x 128 cols ----
    __half* Yout = g_Yh[layer];
#pragma unroll
    for (int i = 0; i < 8; i++) {
        int slot = tid + i * 256;
        int row = slot >> 5;
        int c4 = (slot & 31) * 4;
        int gm = bm + row;
        if (gm < M) {
            *(uint2*)&Yout[(size_t)gm * DD + c4] = *(const uint2*)&Ysh[row * SA + c4];
            if (TO_OUT)
                *(float4*)&extout[(size_t)gm * DD + c4] = *(const float4*)&Hs[row * 132 + c4];
            else
                *(uint2*)&g_Hh[(size_t)gm * DD + c4] = *(const uint2*)&Hsh[row * SA + c4];
        }
    }
}

// ---------------- gather (layer 2): out[n] += sum(Yh1[src] - Rh1[et]) -------
__global__ __launch_bounds__(256) void gather_kernel(float* __restrict__ extout, int M, int layer) {
    int node = blockIdx.x * 8 + (threadIdx.x >> 5);
    if (node >= M) return;
    int lane = threadIdx.x & 31;
    int beg = node ? __ldg(&g_rowstart[node - 1]) : 0;
    int end = __ldg(&g_rowstart[node]);
    const uint2* Yh = (const uint2*)g_Yh[layer];
    const uint2* Rh = (const uint2*)g_Rh[layer];
    float4 acc = make_float4(0.f, 0.f, 0.f, 0.f);
    int i = beg;
    for (; i + 3 < end; i += 4) {
        int e0 = __ldg(&g_edata[i]);
        int e1 = __ldg(&g_edata[i + 1]);
        int e2 = __ldg(&g_edata[i + 2]);
        int e3 = __ldg(&g_edata[i + 3]);
        uint2 y0 = __ldg(&Yh[(size_t)(e0 >> 8) * 32 + lane]);
        uint2 r0 = __ldg(&Rh[(size_t)(e0 & 255) * 32 + lane]);
        uint2 y1 = __ldg(&Yh[(size_t)(e1 >> 8) * 32 + lane]);
        uint2 r1 = __ldg(&Rh[(size_t)(e1 & 255) * 32 + lane]);
        uint2 y2 = __ldg(&Yh[(size_t)(e2 >> 8) * 32 + lane]);
        uint2 r2 = __ldg(&Rh[(size_t)(e2 & 255) * 32 + lane]);
        uint2 y3 = __ldg(&Yh[(size_t)(e3 >> 8) * 32 + lane]);
        uint2 r3 = __ldg(&Rh[(size_t)(e3 & 255) * 32 + lane]);
        acc_edge(acc, y0, r0);
        acc_edge(acc, y1, r1);
        acc_edge(acc, y2, r2);
        acc_edge(acc, y3, r3);
    }
    for (; i < end; i++) {
        int e0 = __ldg(&g_edata[i]);
        uint2 y0 = __ldg(&Yh[(size_t)(e0 >> 8) * 32 + lane]);
        uint2 r0 = __ldg(&Rh[(size_t)(e0 & 255) * 32 + lane]);
        acc_edge(acc, y0, r0);
    }
    int off = lane * 4;
    float4 h = *(float4*)&extout[(size_t)node * DD + off];
    h.x += acc.x; h.y += acc.y; h.z += acc.z; h.w += acc.w;
    *(float4*)&extout[(size_t)node * DD + off] = h;
}

// ---------------------------------------------------------------------------
extern "C" void kernel_launch(void* const* d_in, const int* in_sizes, int n_in,
                              void* d_out, int out_size) {
    const float* x    = (const float*)d_in[0];
    const int*   ei   = (const int*)d_in[1];
    const int*   et   = (const int*)d_in[2];
    const float* W_I1 = (const float*)d_in[3];
    const float* W_O1 = (const float*)d_in[4];
    const float* rel1 = (const float*)d_in[5];
    const float* b1   = (const float*)d_in[6];
    const float* W_I2 = (const float*)d_in[7];
    const float* W_O2 = (const float*)d_in[8];
    const float* rel2 = (const float*)d_in[9];
    const float* b2   = (const float*)d_in[10];
    float* out = (float*)d_out;

    int M = in_sizes[0] / DD;      // 50000
    int E = in_sizes[2];           // 800000
    const int* src = ei;
    const int* dst = ei + E;

    // lazily-created side stream + events (created on the uncaptured
    // correctness call; no device memory involved)
    static cudaStream_t s2 = nullptr;
    static cudaEvent_t evFork = nullptr, evJoin = nullptr;
    if (!s2) {
        cudaStreamCreateWithFlags(&s2, cudaStreamNonBlocking);
        cudaEventCreateWithFlags(&evFork, cudaEventDisableTiming);
        cudaEventCreateWithFlags(&evJoin, cudaEventDisableTiming);
    }

    cudaFuncSetAttribute(gemm_mma_kernel<false, false>,
                         cudaFuncAttributeMaxDynamicSharedMemorySize, SM_BYTES);
    cudaFuncSetAttribute(gemm_mma_kernel<true, true>,
                         cudaFuncAttributeMaxDynamicSharedMemorySize, SM_BYTES);

    int gemm_blocks = (M + 63) / 64;
    int gath_blocks = (M + 7) / 8;

    // ---- fork: CSR build on side stream (needed only from gemm2 on) ----
    cudaEventRecord(evFork, 0);
    cudaStreamWaitEvent(s2, evFork, 0);
    zero_kernel<<<(M + 255) / 256, 256, 0, s2>>>(M);
    hist_kernel<<<(E + 255) / 256, 256, 0, s2>>>(dst, E);
    scan_kernel<<<1, 1024, 0, s2>>>(M);
    fill_kernel<<<(E + 255) / 256, 256, 0, s2>>>(src, dst, et, E);
    cudaEventRecord(evJoin, s2);

    // ---- main stream: layer-1 GEMM chain (independent of CSR) ----
    packb_kernel<<<(256 * DD + 255) / 256, 256>>>(W_I1, W_O1);
    relgemm_kernel<<<NRELMX, DD>>>(rel1, W_I1, 0);
    gemm_mma_kernel<false, false><<<gemm_blocks, 256, SM_BYTES>>>(x, b1, nullptr, M, 0);

    // layer-2 weight prep (B image + R[1]); overlaps the join
    packb_kernel<<<(256 * DD + 255) / 256, 256>>>(W_I2, W_O2);
    relgemm_kernel<<<NRELMX, DD>>>(rel2, W_I2, 1);

    // ---- join CSR, then fused gemm2 (+layer-1 gather) and final gather ----
    cudaStreamWaitEvent(0, evJoin, 0);
    gemm_mma_kernel<true, true><<<gemm_blocks, 256, SM_BYTES>>>(nullptr, b2, out, M, 1);
    gather_kernel<<<gath_blocks, 256>>>(out, M, 1);
}

// round 16
// speedup vs baseline: 1.3170x; 1.3170x over previous
#include <cuda_runtime.h>
#include <cuda_bf16.h>
#include <cuda_fp16.h>
#include <cstdint>

#define NMAX   50000
#define EMAX   800000
#define DD     128
#define NRELMX 237

// SMEM layout (bytes): A/B fp16 row-major stride 136 elems (=272B)
#define SA      136
#define A_OFF   0
#define B_OFF   17408
#define SM_BYTES 52224
// staging (reuses A/B region): Ysh[64][72] fp16; H fp16 [64][72] or fp32 [64][68]
#define YS_OFF  0
#define HS_OFF  9216

// ---------------- static device scratch ------------------------------------
__device__ __half g_Yh[(size_t)NMAX * DD];    // Y fp16 (edge gather source)
__device__ float  g_Hf[(size_t)NMAX * DD];    // layer-1 hidden base fp32
__device__ __half g_Ah[(size_t)NMAX * DD];    // layer-2 A = relu(H+aggr) fp16
__device__ float  g_R[2][NRELMX * DD];        // rel @ W_I^T per layer (fp32)
__device__ __half g_Rh[2][NRELMX * DD];       // fp16 copies (edge gather)
__device__ int    g_cnt[NMAX];
__device__ int    g_rowstart[NMAX + 1];
__device__ int    g_edata[EMAX];              // packed (src<<8)|etype
// Pre-packed B image [256][136] fp16 (interleaved Y/Z cols)
__device__ uint4 g_Bhi[(256 * SA * 2) / 16];

// ---------------- PTX helpers ------------------------------------------------
__device__ __forceinline__ uint32_t smem_to_u32(const void* p) {
    uint32_t a;
    asm("{ .reg .u64 t; cvta.to.shared.u64 t, %1; cvt.u32.u64 %0, t; }" : "=r"(a) : "l"(p));
    return a;
}
__device__ __forceinline__ void ldmx4(uint32_t* r, uint32_t addr) {
    asm volatile("ldmatrix.sync.aligned.m8n8.x4.shared.b16 {%0,%1,%2,%3}, [%4];"
                 : "=r"(r[0]), "=r"(r[1]), "=r"(r[2]), "=r"(r[3]) : "r"(addr));
}
__device__ __forceinline__ void mma16816h(float* d, const uint32_t* a, const uint32_t* b) {
    asm volatile(
        "mma.sync.aligned.m16n8k16.row.col.f32.f16.f16.f32 "
        "{%0,%1,%2,%3}, {%4,%5,%6,%7}, {%8,%9}, {%0,%1,%2,%3};"
        : "+f"(d[0]), "+f"(d[1]), "+f"(d[2]), "+f"(d[3])
        : "r"(a[0]), "r"(a[1]), "r"(a[2]), "r"(a[3]), "r"(b[0]), "r"(b[1]));
}
__device__ __forceinline__ uint32_t pack_h2(__half a, __half b) {
    __half2 t = __halves2half2(a, b);
    return *reinterpret_cast<uint32_t*>(&t);
}
__device__ __forceinline__ void acc_edge(float4& acc, uint2 y, uint2 r) {
    float2 ya = __half22float2(*(__half2*)&y.x), yb = __half22float2(*(__half2*)&y.y);
    float2 ra = __half22float2(*(__half2*)&r.x), rb = __half22float2(*(__half2*)&r.y);
    acc.x += ya.x - ra.x;
    acc.y += ya.y - ra.y;
    acc.z += yb.x - rb.x;
    acc.w += yb.y - rb.y;
}

// ---------------- merged prep: blocks [0,237) relgemm row; [237,493) packb --
// packb: B[r][k], r=2c -> W_I[c][k] (Y), r=2c+1 -> W_O[c][k] (Z)
__global__ __launch_bounds__(DD) void prep_kernel(const float* __restrict__ W_I,
                                                  const float* __restrict__ W_O,
                                                  const float* __restrict__ rel,
                                                  int layer) {
    int b = blockIdx.x;
    int t = threadIdx.x;
    if (b < NRELMX) {
        __shared__ float rr[DD];
        rr[t] = rel[b * DD + t];
        __syncthreads();
        const float4* w4 = (const float4*)(W_I + t * DD);
        float s = 0.f;
#pragma unroll
        for (int kk = 0; kk < DD / 4; kk++) {
            float4 wv = w4[kk];
            s += rr[4 * kk + 0] * wv.x + rr[4 * kk + 1] * wv.y +
                 rr[4 * kk + 2] * wv.z + rr[4 * kk + 3] * wv.w;
        }
        g_R[layer][b * DD + t] = s;
        g_Rh[layer][b * DD + t] = __float2half(s);
    } else {
        int idx = (b - NRELMX) * DD + t;      // 0..32767
        int r = idx >> 7;
        int k = idx & 127;
        int c = r >> 1;
        float v = (r & 1) ? W_O[c * DD + k] : W_I[c * DD + k];
        *(__half*)((char*)g_Bhi + (uint32_t)(r * SA + k) * 2u) = __float2half(v);
    }
}

// ---------------- edge CSR build --------------------------------------------
__global__ void zero_kernel(int M) {
    int i = blockIdx.x * blockDim.x + threadIdx.x;
    if (i < M) g_cnt[i] = 0;
}
__global__ void hist_kernel(const int* __restrict__ dst, int E) {
    int e = blockIdx.x * blockDim.x + threadIdx.x;
    if (e < E) atomicAdd(&g_cnt[dst[e]], 1);
}
__global__ __launch_bounds__(1024) void scan_kernel(int M) {
    __shared__ int ssum[1024];
    int t = threadIdx.x;
    const int CH = (M + 1023) / 1024;
    int beg = t * CH;
    int s = 0;
    for (int i = 0; i < CH; i++) {
        int idx = beg + i;
        if (idx < M) s += g_cnt[idx];
    }
    ssum[t] = s;
    __syncthreads();
    for (int off = 1; off < 1024; off <<= 1) {
        int v = (t >= off) ? ssum[t - off] : 0;
        __syncthreads();
        ssum[t] += v;
        __syncthreads();
    }
    int pre = (t == 0) ? 0 : ssum[t - 1];
    for (int i = 0; i < CH; i++) {
        int idx = beg + i;
        if (idx < M) {
            g_rowstart[idx] = pre;
            pre += g_cnt[idx];
        }
    }
    if (t == 1023) g_rowstart[M] = pre;
}
__global__ void fill_kernel(const int* __restrict__ src,
                            const int* __restrict__ dst,
                            const int* __restrict__ et, int E) {
    int e = blockIdx.x * blockDim.x + threadIdx.x;
    if (e >= E) return;
    int d = dst[e];
    int pos = atomicAdd(&g_rowstart[d], 1);
    g_edata[pos] = (src[e] << 8) | et[e];
}

// ---------------- HMMA GEMM: BM=64, BN=128 n' (64 real cols), occ 3 ---------
// single-term fp16: D = fp16(A) * fp16(B), fp32 accum
// FROM_AH: A is pre-converted fp16 (g_Ah); else fp32 Ain
template <bool FROM_AH, bool TO_OUT>
__global__ __launch_bounds__(256, 3)
void gemm_mma_kernel(const float* __restrict__ Ain,
                     const float* __restrict__ bias,
                     float* __restrict__ extout, int M, int layer) {
    extern __shared__ char smem[];
    uint32_t sb = smem_to_u32(smem);
    int tid = threadIdx.x;
    int wid = tid >> 5;
    int lane = tid & 31;
    int bm = blockIdx.x * 64;
    int bn = blockIdx.y;           // n-half (0/1)

    // ---- B copy: rows bn*128..+127 of packed image = 2176 uint4 ----
    {
        const uint4* sbh = g_Bhi + (size_t)bn * 2176;
        uint4* bh = (uint4*)(smem + B_OFF);
#pragma unroll
        for (int i = 0; i < 9; i++) {
            int idx = tid + i * 256;
            if (idx < 2176) bh[idx] = sbh[idx];
        }
    }

    // ---- A load (coalesced): 64x128 ----
    if (FROM_AH) {
#pragma unroll
        for (int i = 0; i < 8; i++) {
            int slot = tid + i * 256;
            int row = slot >> 5;
            int c4 = (slot & 31) * 4;
            int gm = bm + row;
            uint2 hv = make_uint2(0u, 0u);
            if (gm < M) hv = *(const uint2*)&g_Ah[(size_t)gm * DD + c4];
            *(uint2*)(smem + A_OFF + (uint32_t)(row * SA + c4) * 2u) = hv;
        }
    } else {
#pragma unroll
        for (int i = 0; i < 8; i++) {
            int slot = tid + i * 256;
            int row = slot >> 5;
            int c4 = (slot & 31) * 4;
            int gm = bm + row;
            float4 v = make_float4(0.f, 0.f, 0.f, 0.f);
            if (gm < M) v = *(const float4*)(Ain + (size_t)gm * DD + c4);
            *(uint2*)(smem + A_OFF + (uint32_t)(row * SA + c4) * 2u) =
                make_uint2(pack_h2(__float2half(v.x), __float2half(v.y)),
                           pack_h2(__float2half(v.z), __float2half(v.w)));
        }
    }
    __syncthreads();

    int wm = wid & 1;
    int wn = wid >> 1;
    int grp = lane >> 3;
    int r8 = lane & 7;

    float acc[2][4][4];
#pragma unroll
    for (int mt = 0; mt < 2; mt++)
#pragma unroll
        for (int nt = 0; nt < 4; nt++)
#pragma unroll
            for (int q = 0; q < 4; q++) acc[mt][nt][q] = 0.f;

    uint32_t a_off = sb + A_OFF + (uint32_t)((wm * 32 + (grp & 1) * 8 + r8) * SA + (grp >> 1) * 8) * 2u;
    uint32_t b_off = sb + B_OFF + (uint32_t)((wn * 32 + (grp >> 1) * 8 + r8) * SA + (grp & 1) * 8) * 2u;

#pragma unroll
    for (int ks = 0; ks < 8; ks++) {
        uint32_t kb = (uint32_t)(ks * 16 * 2);
        uint32_t afh[2][4];
#pragma unroll
        for (int mt = 0; mt < 2; mt++)
            ldmx4(afh[mt], a_off + (uint32_t)(mt * 16 * SA * 2) + kb);
        uint32_t bfh[4][2];
#pragma unroll
        for (int np = 0; np < 2; np++) {
            uint32_t t[4];
            ldmx4(t, b_off + (uint32_t)(np * 16 * SA * 2) + kb);
            bfh[np * 2][0] = t[0]; bfh[np * 2][1] = t[1];
            bfh[np * 2 + 1][0] = t[2]; bfh[np * 2 + 1][1] = t[3];
        }
#pragma unroll
        for (int mt = 0; mt < 2; mt++)
#pragma unroll
            for (int nt = 0; nt < 4; nt++)
                mma16816h(acc[mt][nt], afh[mt], bfh[nt]);
    }
    __syncthreads();   // done with A/B smem; reuse for staging

    // ---- stage: Ysh[64][72] fp16; H fp32 [64][68] ----
    __half* Ysh = (__half*)(smem + YS_OFF);
    float*  Hs  = (float*)(smem + HS_OFF);
    const float* Rb = g_R[layer];
#pragma unroll
    for (int nt = 0; nt < 4; nt++) {
        int cl = wn * 16 + nt * 4 + (lane & 3);
        int cg = bn * 64 + cl;
        float rb = bias[cg] - Rb[cg];
#pragma unroll
        for (int mt = 0; mt < 2; mt++) {
            int r0 = wm * 32 + mt * 16 + (lane >> 2);
            float y0 = acc[mt][nt][0], z0 = acc[mt][nt][1];
            float y1 = acc[mt][nt][2], z1 = acc[mt][nt][3];
            Ysh[r0 * 72 + cl] = __float2half(y0);
            Ysh[(r0 + 8) * 72 + cl] = __float2half(y1);
            Hs[r0 * 68 + cl] = y0 + z0 + rb;
            Hs[(r0 + 8) * 68 + cl] = y1 + z1 + rb;
        }
    }
    __syncthreads();

    // ---- coalesced copy-out ----
    float* H = TO_OUT ? extout : g_Hf;
#pragma unroll
    for (int i = 0; i < 4; i++) {
        int slot = tid + i * 256;
        int row = slot >> 4;
        int c4 = (slot & 15) * 4;
        int gm = bm + row;
        if (gm < M) {
            *(uint2*)&g_Yh[(size_t)gm * DD + bn * 64 + c4] = *(const uint2*)&Ysh[row * 72 + c4];
            *(float4*)&H[(size_t)gm * DD + bn * 64 + c4] = *(const float4*)&Hs[row * 68 + c4];
        }
    }
}

// ---------------- gather layer 1: g_Ah[n] = fp16(relu(Hf[n] + aggr)) --------
__global__ __launch_bounds__(256) void gather1_kernel(int M) {
    int node = blockIdx.x * 8 + (threadIdx.x >> 5);
    if (node >= M) return;
    int lane = threadIdx.x & 31;
    int beg = node ? __ldg(&g_rowstart[node - 1]) : 0;
    int end = __ldg(&g_rowstart[node]);
    const uint2* Yh = (const uint2*)g_Yh;
    const uint2* Rh = (const uint2*)g_Rh[0];
    float4 acc = make_float4(0.f, 0.f, 0.f, 0.f);
    int i = beg;
    for (; i + 3 < end; i += 4) {
        int e0 = __ldg(&g_edata[i]);
        int e1 = __ldg(&g_edata[i + 1]);
        int e2 = __ldg(&g_edata[i + 2]);
        int e3 = __ldg(&g_edata[i + 3]);
        uint2 y0 = __ldg(&Yh[(size_t)(e0 >> 8) * 32 + lane]);
        uint2 r0 = __ldg(&Rh[(size_t)(e0 & 255) * 32 + lane]);
        uint2 y1 = __ldg(&Yh[(size_t)(e1 >> 8) * 32 + lane]);
        uint2 r1 = __ldg(&Rh[(size_t)(e1 & 255) * 32 + lane]);
        uint2 y2 = __ldg(&Yh[(size_t)(e2 >> 8) * 32 + lane]);
        uint2 r2 = __ldg(&Rh[(size_t)(e2 & 255) * 32 + lane]);
        uint2 y3 = __ldg(&Yh[(size_t)(e3 >> 8) * 32 + lane]);
        uint2 r3 = __ldg(&Rh[(size_t)(e3 & 255) * 32 + lane]);
        acc_edge(acc, y0, r0);
        acc_edge(acc, y1, r1);
        acc_edge(acc, y2, r2);
        acc_edge(acc, y3, r3);
    }
    for (; i < end; i++) {
        int e0 = __ldg(&g_edata[i]);
        uint2 y0 = __ldg(&Yh[(size_t)(e0 >> 8) * 32 + lane]);
        uint2 r0 = __ldg(&Rh[(size_t)(e0 & 255) * 32 + lane]);
        acc_edge(acc, y0, r0);
    }
    int off = lane * 4;
    float4 h = *(const float4*)&g_Hf[(size_t)node * DD + off];
    float v0 = fmaxf(h.x + acc.x, 0.f);
    float v1 = fmaxf(h.y + acc.y, 0.f);
    float v2 = fmaxf(h.z + acc.z, 0.f);
    float v3 = fmaxf(h.w + acc.w, 0.f);
    *(uint2*)&g_Ah[(size_t)node * DD + off] =
        make_uint2(pack_h2(__float2half(v0), __float2half(v1)),
                   pack_h2(__float2half(v2), __float2half(v3)));
}

// ---------------- gather layer 2: out[n] += aggr ----------------------------
__global__ __launch_bounds__(256) void gather2_kernel(float* __restrict__ extout, int M) {
    int node = blockIdx.x * 8 + (threadIdx.x >> 5);
    if (node >= M) return;
    int lane = threadIdx.x & 31;
    int beg = node ? __ldg(&g_rowstart[node - 1]) : 0;
    int end = __ldg(&g_rowstart[node]);
    const uint2* Yh = (const uint2*)g_Yh;
    const uint2* Rh = (const uint2*)g_Rh[1];
    float4 acc = make_float4(0.f, 0.f, 0.f, 0.f);
    int i = beg;
    for (; i + 3 < end; i += 4) {
        int e0 = __ldg(&g_edata[i]);
        int e1 = __ldg(&g_edata[i + 1]);
        int e2 = __ldg(&g_edata[i + 2]);
        int e3 = __ldg(&g_edata[i + 3]);
        uint2 y0 = __ldg(&Yh[(size_t)(e0 >> 8) * 32 + lane]);
        uint2 r0 = __ldg(&Rh[(size_t)(e0 & 255) * 32 + lane]);
        uint2 y1 = __ldg(&Yh[(size_t)(e1 >> 8) * 32 + lane]);
        uint2 r1 = __ldg(&Rh[(size_t)(e1 & 255) * 32 + lane]);
        uint2 y2 = __ldg(&Yh[(size_t)(e2 >> 8) * 32 + lane]);
        uint2 r2 = __ldg(&Rh[(size_t)(e2 & 255) * 32 + lane]);
        uint2 y3 = __ldg(&Yh[(size_t)(e3 >> 8) * 32 + lane]);
        uint2 r3 = __ldg(&Rh[(size_t)(e3 & 255) * 32 + lane]);
        acc_edge(acc, y0, r0);
        acc_edge(acc, y1, r1);
        acc_edge(acc, y2, r2);
        acc_edge(acc, y3, r3);
    }
    for (; i < end; i++) {
        int e0 = __ldg(&g_edata[i]);
        uint2 y0 = __ldg(&Yh[(size_t)(e0 >> 8) * 32 + lane]);
        uint2 r0 = __ldg(&Rh[(size_t)(e0 & 255) * 32 + lane]);
        acc_edge(acc, y0, r0);
    }
    int off = lane * 4;
    float4 h = *(float4*)&extout[(size_t)node * DD + off];
    h.x += acc.x; h.y += acc.y; h.z += acc.z; h.w += acc.w;
    *(float4*)&extout[(size_t)node * DD + off] = h;
}

// ---------------------------------------------------------------------------
extern "C" void kernel_launch(void* const* d_in, const int* in_sizes, int n_in,
                              void* d_out, int out_size) {
    const float* x    = (const float*)d_in[0];
    const int*   ei   = (const int*)d_in[1];
    const int*   et   = (const int*)d_in[2];
    const float* W_I1 = (const float*)d_in[3];
    const float* W_O1 = (const float*)d_in[4];
    const float* rel1 = (const float*)d_in[5];
    const float* b1   = (const float*)d_in[6];
    const float* W_I2 = (const float*)d_in[7];
    const float* W_O2 = (const float*)d_in[8];
    const float* rel2 = (const float*)d_in[9];
    const float* b2   = (const float*)d_in[10];
    float* out = (float*)d_out;

    int M = in_sizes[0] / DD;      // 50000
    int E = in_sizes[2];           // 800000
    const int* src = ei;
    const int* dst = ei + E;

    static cudaStream_t s2 = nullptr;
    static cudaEvent_t evFork = nullptr, evJoin = nullptr;
    if (!s2) {
        cudaStreamCreateWithFlags(&s2, cudaStreamNonBlocking);
        cudaEventCreateWithFlags(&evFork, cudaEventDisableTiming);
        cudaEventCreateWithFlags(&evJoin, cudaEventDisableTiming);
    }

    cudaFuncSetAttribute(gemm_mma_kernel<false, false>,
                         cudaFuncAttributeMaxDynamicSharedMemorySize, SM_BYTES);
    cudaFuncSetAttribute(gemm_mma_kernel<true, true>,
                         cudaFuncAttributeMaxDynamicSharedMemorySize, SM_BYTES);

    dim3 ggemm((M + 63) / 64, 2);
    int gath_blocks = (M + 7) / 8;
    int prep_blocks = NRELMX + (256 * DD) / DD;  // 237 + 256

    // ---- fork: CSR build on side stream (only gathers depend on it) ----
    cudaEventRecord(evFork, 0);
    cudaStreamWaitEvent(s2, evFork, 0);
    zero_kernel<<<(M + 255) / 256, 256, 0, s2>>>(M);
    hist_kernel<<<(E + 255) / 256, 256, 0, s2>>>(dst, E);
    scan_kernel<<<1, 1024, 0, s2>>>(M);
    fill_kernel<<<(E + 255) / 256, 256, 0, s2>>>(src, dst, et, E);
    cudaEventRecord(evJoin, s2);

    // ---- main stream: layer-1 GEMM chain ----
    prep_kernel<<<prep_blocks, DD>>>(W_I1, W_O1, rel1, 0);
    gemm_mma_kernel<false, false><<<ggemm, 256, SM_BYTES>>>(x, b1, nullptr, M, 0);

    // layer-2 weight prep (B image + R[1]); overlaps the join
    prep_kernel<<<prep_blocks, DD>>>(W_I2, W_O2, rel2, 1);

    // ---- join CSR, then gather1 / gemm2 / gather2 ----
    cudaStreamWaitEvent(0, evJoin, 0);
    gather1_kernel<<<gath_blocks, 256>>>(M);
    gemm_mma_kernel<true, true><<<ggemm, 256, SM_BYTES>>>(nullptr, b2, out, M, 1);
    gather2_kernel<<<gath_blocks, 256>>>(out, M);
}